// round 10
// baseline (speedup 1.0000x reference)
#include <cuda_runtime.h>
#include <cuda_bf16.h>
#include <stdint.h>
#include <math.h>

#define NN 10000        // nodes
#define EE 320000       // raw edges
#define ET 330000       // edges + self loops
#define FDIM 512        // H*C for all layers
#define SLOPE 0.2f

// ---------------- scratch (static device globals) ----------------------------
__device__ float          g_feat[NN * FDIM];
__device__ __nv_bfloat16  g_hb  [NN * FDIM];   // h buffer in bf16 (gather side)
__device__ float          g_als [NN * 4];
__device__ float          g_ald [NN * 4];
__device__ int            g_off [NN + 1];
__device__ int            g_pos [NN];
__device__ int            g_csrc[ET];

// ======================= CSR build ===========================================
__global__ void zero_counts(int* cnt) {
    int i = blockIdx.x * blockDim.x + threadIdx.x;
    if (i < NN) cnt[i] = 0;
}

__global__ void count_deg(const int* __restrict__ ei, int* __restrict__ cnt) {
    int e = blockIdx.x * blockDim.x + threadIdx.x;
    if (e >= ET) return;
    int d = (e < EE) ? ei[EE + e] : (e - EE);
    atomicAdd(&cnt[d], 1);
}

#define SCHUNK 10   // 1024 * 10 >= NN
__global__ void scan_kernel(const int* __restrict__ cnt,
                            int* __restrict__ off, int* __restrict__ pos) {
    __shared__ int part[1024];
    int t = threadIdx.x;
    int base = t * SCHUNK;
    int local[SCHUNK];
    int s = 0;
    #pragma unroll
    for (int i = 0; i < SCHUNK; i++) {
        int idx = base + i;
        local[i] = s;
        s += (idx < NN) ? cnt[idx] : 0;
    }
    part[t] = s;
    __syncthreads();
    for (int o = 1; o < 1024; o <<= 1) {
        int v = (t >= o) ? part[t - o] : 0;
        __syncthreads();
        part[t] += v;
        __syncthreads();
    }
    int prev = (t > 0) ? part[t - 1] : 0;
    #pragma unroll
    for (int i = 0; i < SCHUNK; i++) {
        int idx = base + i;
        if (idx < NN) {
            int o = prev + local[i];
            off[idx] = o;
            pos[idx] = o;
        }
    }
    if (t == 1023) off[NN] = part[1023];
}

__global__ void scatter_edges(const int* __restrict__ ei,
                              int* __restrict__ pos, int* __restrict__ csrc) {
    int e = blockIdx.x * blockDim.x + threadIdx.x;
    if (e >= ET) return;
    int s, d;
    if (e < EE) { s = ei[e]; d = ei[EE + e]; } else { s = d = e - EE; }
    int p = atomicAdd(&pos[d], 1);
    csrc[p] = s;
}

// ======================= tf32 tensor-core GEMM (cp.async 2-stage) ============
__device__ __forceinline__ uint32_t f2tf(float f) {
    uint32_t r; asm("cvt.rna.tf32.f32 %0, %1;" : "=r"(r) : "f"(f)); return r;
}

__device__ __forceinline__ void mma8(float* d, const uint32_t* a, const uint32_t* b) {
    asm volatile("mma.sync.aligned.m16n8k8.row.col.f32.tf32.tf32.f32 "
                 "{%0,%1,%2,%3},{%4,%5,%6,%7},{%8,%9},{%0,%1,%2,%3};"
                 : "+f"(d[0]), "+f"(d[1]), "+f"(d[2]), "+f"(d[3])
                 : "r"(a[0]), "r"(a[1]), "r"(a[2]), "r"(a[3]),
                   "r"(b[0]), "r"(b[1]));
}

__device__ __forceinline__ void cp16(uint32_t dst, const void* src, int bytes) {
    asm volatile("cp.async.cg.shared.global [%0], [%1], 16, %2;"
                 :: "r"(dst), "l"(src), "r"(bytes));
}
__device__ __forceinline__ void cp_commit() {
    asm volatile("cp.async.commit_group;");
}
template<int N> __device__ __forceinline__ void cp_wait() {
    asm volatile("cp.async.wait_group %0;" :: "n"(N));
}

#define APAD 20   // words per A row (16 + 4) -> conflict-free fragment reads
#define BPAD 136  // words per B row (128 + 8)

__global__ __launch_bounds__(256, 2)
void tf32gemm(const float* __restrict__ A, const float* __restrict__ W,
              __nv_bfloat16* __restrict__ C, int n, int K) {
    __shared__ float As[2][128 * APAD];
    __shared__ float Bs[2][16 * BPAD];

    int tid = threadIdx.x;
    int wid = tid >> 5, lane = tid & 31;
    int gid = lane >> 2, tig = lane & 3;
    int mW = (wid & 1) * 64;
    int nW = (wid >> 1) * 32;
    int rowBase = blockIdx.y * 128;
    int colBase = blockIdx.x * 128;

    float acc[4][4][4] = {};

    int nk = K >> 4;

    auto load_tiles = [&](int s, int k0) {
        #pragma unroll
        for (int j = 0; j < 2; j++) {
            int i = tid + j * 256;
            int r = i >> 2, kq = (i & 3) * 4;
            int grow = rowBase + r;
            int ok = (grow < n) ? 16 : 0;
            const float* src = A + (size_t)(ok ? grow : 0) * K + k0 + kq;
            uint32_t dst = (uint32_t)__cvta_generic_to_shared(&As[s][r * APAD + kq]);
            cp16(dst, src, ok);
        }
        #pragma unroll
        for (int j = 0; j < 2; j++) {
            int i = tid + j * 256;
            int kr = i >> 5, cq = (i & 31) * 4;
            const float* src = W + (size_t)(k0 + kr) * FDIM + colBase + cq;
            uint32_t dst = (uint32_t)__cvta_generic_to_shared(&Bs[s][kr * BPAD + cq]);
            cp16(dst, src, 16);
        }
    };

    load_tiles(0, 0);
    cp_commit();

    for (int kt = 0; kt < nk; kt++) {
        int cur = kt & 1;
        if (kt + 1 < nk) {
            load_tiles(cur ^ 1, (kt + 1) << 4);
            cp_commit();
            cp_wait<1>();
        } else {
            cp_wait<0>();
        }
        __syncthreads();

        #pragma unroll
        for (int kk = 0; kk < 16; kk += 8) {
            uint32_t af[4][4], bf[4][2];
            #pragma unroll
            for (int i = 0; i < 4; i++) {
                int r = mW + i * 16 + gid;
                af[i][0] = f2tf(As[cur][r * APAD + kk + tig]);
                af[i][1] = f2tf(As[cur][(r + 8) * APAD + kk + tig]);
                af[i][2] = f2tf(As[cur][r * APAD + kk + tig + 4]);
                af[i][3] = f2tf(As[cur][(r + 8) * APAD + kk + tig + 4]);
            }
            #pragma unroll
            for (int j = 0; j < 4; j++) {
                int c = nW + j * 8 + gid;
                bf[j][0] = f2tf(Bs[cur][(kk + tig) * BPAD + c]);
                bf[j][1] = f2tf(Bs[cur][(kk + tig + 4) * BPAD + c]);
            }
            #pragma unroll
            for (int i = 0; i < 4; i++)
                #pragma unroll
                for (int j = 0; j < 4; j++)
                    mma8(acc[i][j], af[i], bf[j]);
        }
        __syncthreads();
    }

    // ---- epilogue: write bf16 ----
    #pragma unroll
    for (int i = 0; i < 4; i++) {
        int r0 = rowBase + mW + i * 16 + gid;
        int r1 = r0 + 8;
        #pragma unroll
        for (int j = 0; j < 4; j++) {
            int c = colBase + nW + j * 8 + tig * 2;
            if (r0 < n) *(__nv_bfloat162*)(C + (size_t)r0 * FDIM + c) =
                __float22bfloat162_rn(make_float2(acc[i][j][0], acc[i][j][1]));
            if (r1 < n) *(__nv_bfloat162*)(C + (size_t)r1 * FDIM + c) =
                __float22bfloat162_rn(make_float2(acc[i][j][2], acc[i][j][3]));
        }
    }
}

// ======================= per-node attention dots (bf16 h) ====================
__global__ void attn_kernel(const __nv_bfloat16* __restrict__ h,
                            const float* __restrict__ a_src,
                            const float* __restrict__ a_dst,
                            float* __restrict__ als, float* __restrict__ ald,
                            int H, int C) {
    int w = (blockIdx.x * blockDim.x + threadIdx.x) >> 5;
    int lane = threadIdx.x & 31;
    if (w >= NN * H) return;
    int n = w / H, hh = w - n * H;
    const __nv_bfloat16* hp = h + (size_t)n * FDIM + hh * C;
    const float* asp = a_src + hh * C;
    const float* adp = a_dst + hh * C;
    float s = 0.f, d = 0.f;
    for (int c = lane * 2; c < C; c += 64) {
        float2 v = __bfloat1622float2(*(const __nv_bfloat162*)(hp + c));
        s += v.x * asp[c] + v.y * asp[c + 1];
        d += v.x * adp[c] + v.y * adp[c + 1];
    }
    #pragma unroll
    for (int o = 16; o > 0; o >>= 1) {
        s += __shfl_down_sync(0xffffffffu, s, o);
        d += __shfl_down_sync(0xffffffffu, d, o);
    }
    if (lane == 0) { als[w] = s; ald[w] = d; }
}

// ======================= fused single-pass softmax + aggregation =============
__device__ __forceinline__ float leaky(float l) {
    return (l > 0.f) ? l : SLOPE * l;
}

__device__ __forceinline__ float4 ld_bf4(const __nv_bfloat16* p) {
    uint2 raw = *(const uint2*)p;                 // 4 bf16 = 8 bytes
    __nv_bfloat162 p0 = *(__nv_bfloat162*)&raw.x;
    __nv_bfloat162 p1 = *(__nv_bfloat162*)&raw.y;
    float2 f0 = __bfloat1622float2(p0);
    float2 f1 = __bfloat1622float2(p1);
    return make_float4(f0.x, f0.y, f1.x, f1.y);
}

__global__ void gat_agg(const int* __restrict__ off, const int* __restrict__ csrc,
                        const __nv_bfloat16* __restrict__ h,
                        const float* __restrict__ als, const float* __restrict__ ald,
                        const float* __restrict__ bias,
                        float* __restrict__ out, int H, int C, int relu) {
    int dst = blockIdx.x;
    int w = threadIdx.x >> 5;
    int lane = threadIdx.x & 31;
    int cpw = C >> 7;
    int head = w / cpw;
    int chunk = w - head * cpw;

    int beg = off[dst], end = off[dst + 1];
    float ad = ald[dst * H + head];

    float4 acc = make_float4(0.f, 0.f, 0.f, 0.f);
    float sum = 0.f;
    int cbase = head * C + chunk * 128 + lane * 4;

    int e = beg;
    for (; e + 4 <= end; e += 4) {
        int s0 = csrc[e], s1 = csrc[e+1], s2 = csrc[e+2], s3 = csrc[e+3];
        float e0 = __expf(leaky(als[s0 * H + head] + ad));
        float e1 = __expf(leaky(als[s1 * H + head] + ad));
        float e2 = __expf(leaky(als[s2 * H + head] + ad));
        float e3 = __expf(leaky(als[s3 * H + head] + ad));
        float4 v0 = ld_bf4(h + (size_t)s0 * FDIM + cbase);
        float4 v1 = ld_bf4(h + (size_t)s1 * FDIM + cbase);
        float4 v2 = ld_bf4(h + (size_t)s2 * FDIM + cbase);
        float4 v3 = ld_bf4(h + (size_t)s3 * FDIM + cbase);
        sum += (e0 + e1) + (e2 + e3);
        acc.x += v0.x*e0 + v1.x*e1 + v2.x*e2 + v3.x*e3;
        acc.y += v0.y*e0 + v1.y*e1 + v2.y*e2 + v3.y*e3;
        acc.z += v0.z*e0 + v1.z*e1 + v2.z*e2 + v3.z*e3;
        acc.w += v0.w*e0 + v1.w*e1 + v2.w*e2 + v3.w*e3;
    }
    for (; e < end; e++) {
        int s = csrc[e];
        float e0 = __expf(leaky(als[s * H + head] + ad));
        float4 v = ld_bf4(h + (size_t)s * FDIM + cbase);
        sum += e0;
        acc.x += v.x * e0; acc.y += v.y * e0;
        acc.z += v.z * e0; acc.w += v.w * e0;
    }

    float inv = 1.f / sum;
    float4 bv = *(const float4*)(bias + cbase);
    acc.x = acc.x * inv + bv.x;
    acc.y = acc.y * inv + bv.y;
    acc.z = acc.z * inv + bv.z;
    acc.w = acc.w * inv + bv.w;
    if (relu) {
        acc.x = fmaxf(acc.x, 0.f); acc.y = fmaxf(acc.y, 0.f);
        acc.z = fmaxf(acc.z, 0.f); acc.w = fmaxf(acc.w, 0.f);
    }
    *(float4*)(out + (size_t)dst * FDIM + cbase) = acc;
}

// ======================= host-side driver ====================================
static void run_layer(const float* A, int K, const float* W,
                      const float* a_src, const float* a_dst, const float* bias,
                      int H, int C,
                      const int* off, const int* csrc,
                      __nv_bfloat16* hbuf, float* aggout,
                      float* als, float* ald, int relu) {
    dim3 gg(FDIM / 128, (NN + 127) / 128);
    tf32gemm<<<gg, 256>>>(A, W, hbuf, NN, K);

    int warpsA = NN * H;
    attn_kernel<<<(warpsA * 32 + 255) / 256, 256>>>(hbuf, a_src, a_dst, als, ald, H, C);

    gat_agg<<<NN, 128>>>(off, csrc, hbuf, als, ald, bias, aggout, H, C, relu);
}

extern "C" void kernel_launch(void* const* d_in, const int* in_sizes, int n_in,
                              void* d_out, int out_size) {
    const float* x   = (const float*)d_in[0];
    const int*   ei  = (const int*)  d_in[1];
    const float* W1  = (const float*)d_in[2];
    const float* as1 = (const float*)d_in[3];
    const float* ad1 = (const float*)d_in[4];
    const float* b1  = (const float*)d_in[5];
    const float* W2  = (const float*)d_in[6];
    const float* as2 = (const float*)d_in[7];
    const float* ad2 = (const float*)d_in[8];
    const float* b2  = (const float*)d_in[9];
    const float* W3  = (const float*)d_in[10];
    const float* as3 = (const float*)d_in[11];
    const float* ad3 = (const float*)d_in[12];
    const float* b3  = (const float*)d_in[13];
    float* out = (float*)d_out;

    float *feat, *als, *ald;
    __nv_bfloat16* hbuf;
    int *off, *pos, *csrc;
    cudaGetSymbolAddress((void**)&feat, g_feat);
    cudaGetSymbolAddress((void**)&hbuf, g_hb);
    cudaGetSymbolAddress((void**)&als,  g_als);
    cudaGetSymbolAddress((void**)&ald,  g_ald);
    cudaGetSymbolAddress((void**)&off,  g_off);
    cudaGetSymbolAddress((void**)&pos,  g_pos);
    cudaGetSymbolAddress((void**)&csrc, g_csrc);

    // ---- build CSR (dst-sorted) ----
    zero_counts<<<(NN + 255) / 256, 256>>>(pos);
    count_deg<<<(ET + 255) / 256, 256>>>(ei, pos);
    scan_kernel<<<1, 1024>>>(pos, off, pos);
    scatter_edges<<<(ET + 255) / 256, 256>>>(ei, pos, csrc);

    // ---- 3 GAT layers ----
    run_layer(x,    128, W1, as1, ad1, b1, 4, 128, off, csrc, hbuf, feat, als, ald, 1);
    run_layer(feat, 512, W2, as2, ad2, b2, 4, 128, off, csrc, hbuf, feat, als, ald, 1);
    run_layer(feat, 512, W3, as3, ad3, b3, 1, 512, off, csrc, hbuf, out,  als, ald, 0);
}

// round 12
// speedup vs baseline: 1.0059x; 1.0059x over previous
#include <cuda_runtime.h>
#include <stdint.h>
#include <math.h>

#define NN 10000        // nodes
#define EE 320000       // raw edges
#define ET 330000       // edges + self loops
#define FDIM 512        // H*C for all layers
#define SLOPE 0.2f

// ---------------- scratch (static device globals) ----------------------------
__device__ float g_feat [NN * FDIM];
__device__ float g_h    [NN * FDIM];
__device__ float g_als  [NN * 4];
__device__ float g_ald  [NN * 4];
__device__ int   g_off  [NN + 1];
__device__ int   g_pos  [NN];
__device__ int   g_csrc [ET];

// ======================= CSR build ===========================================
__global__ void zero_counts(int* cnt) {
    int i = blockIdx.x * blockDim.x + threadIdx.x;
    if (i < NN) cnt[i] = 0;
}

// 4 edges per thread -> 4 outstanding atomics (ATOMG latency ~318cyc, MLP=4)
__global__ void count_deg(const int* __restrict__ ei, int* __restrict__ cnt) {
    int e0 = (blockIdx.x * blockDim.x + threadIdx.x) * 4;
    #pragma unroll
    for (int j = 0; j < 4; j++) {
        int e = e0 + j;
        if (e < ET) {
            int d = (e < EE) ? ei[EE + e] : (e - EE);
            atomicAdd(&cnt[d], 1);
        }
    }
}

#define SCHUNK 10   // 1024 * 10 >= NN
__global__ void scan_kernel(const int* __restrict__ cnt,
                            int* __restrict__ off, int* __restrict__ pos) {
    __shared__ int part[1024];
    int t = threadIdx.x;
    int base = t * SCHUNK;
    int local[SCHUNK];
    int s = 0;
    #pragma unroll
    for (int i = 0; i < SCHUNK; i++) {
        int idx = base + i;
        local[i] = s;
        s += (idx < NN) ? cnt[idx] : 0;
    }
    part[t] = s;
    __syncthreads();
    for (int o = 1; o < 1024; o <<= 1) {
        int v = (t >= o) ? part[t - o] : 0;
        __syncthreads();
        part[t] += v;
        __syncthreads();
    }
    int prev = (t > 0) ? part[t - 1] : 0;
    #pragma unroll
    for (int i = 0; i < SCHUNK; i++) {
        int idx = base + i;
        if (idx < NN) {
            int o = prev + local[i];
            off[idx] = o;
            pos[idx] = o;
        }
    }
    if (t == 1023) off[NN] = part[1023];
}

__global__ void scatter_edges(const int* __restrict__ ei,
                              int* __restrict__ pos, int* __restrict__ csrc) {
    int e0 = (blockIdx.x * blockDim.x + threadIdx.x) * 4;
    #pragma unroll
    for (int j = 0; j < 4; j++) {
        int e = e0 + j;
        if (e < ET) {
            int s, d;
            if (e < EE) { s = ei[e]; d = ei[EE + e]; } else { s = d = e - EE; }
            int p = atomicAdd(&pos[d], 1);
            csrc[p] = s;
        }
    }
}

// ======================= tf32 tensor-core GEMM (cp.async 3-stage) ============
__device__ __forceinline__ uint32_t f2tf(float f) {
    uint32_t r; asm("cvt.rna.tf32.f32 %0, %1;" : "=r"(r) : "f"(f)); return r;
}

__device__ __forceinline__ void mma8(float* d, const uint32_t* a, const uint32_t* b) {
    asm volatile("mma.sync.aligned.m16n8k8.row.col.f32.tf32.tf32.f32 "
                 "{%0,%1,%2,%3},{%4,%5,%6,%7},{%8,%9},{%0,%1,%2,%3};"
                 : "+f"(d[0]), "+f"(d[1]), "+f"(d[2]), "+f"(d[3])
                 : "r"(a[0]), "r"(a[1]), "r"(a[2]), "r"(a[3]),
                   "r"(b[0]), "r"(b[1]));
}

__device__ __forceinline__ void cp16(uint32_t dst, const void* src, int bytes) {
    asm volatile("cp.async.cg.shared.global [%0], [%1], 16, %2;"
                 :: "r"(dst), "l"(src), "r"(bytes));
}
__device__ __forceinline__ void cp_commit() {
    asm volatile("cp.async.commit_group;");
}
template<int N> __device__ __forceinline__ void cp_wait() {
    asm volatile("cp.async.wait_group %0;" :: "n"(N));
}

#define APAD 20   // words per A row (16 + 4) -> conflict-free fragment reads
#define BPAD 136  // words per B row (128 + 8)
#define NSTG 3

__global__ __launch_bounds__(256, 2)
void tf32gemm(const float* __restrict__ A, const float* __restrict__ W,
              float* __restrict__ C, int n, int K) {
    __shared__ float As[NSTG][128 * APAD];
    __shared__ float Bs[NSTG][16 * BPAD];

    int tid = threadIdx.x;
    int wid = tid >> 5, lane = tid & 31;
    int gid = lane >> 2, tig = lane & 3;
    int mW = (wid & 1) * 64;
    int nW = (wid >> 1) * 32;
    int rowBase = blockIdx.y * 128;
    int colBase = blockIdx.x * 128;

    float acc[4][4][4] = {};

    int nk = K >> 4;

    auto load_tiles = [&](int s, int k0) {
        #pragma unroll
        for (int j = 0; j < 2; j++) {
            int i = tid + j * 256;
            int r = i >> 2, kq = (i & 3) * 4;
            int grow = rowBase + r;
            int ok = (grow < n) ? 16 : 0;
            const float* src = A + (size_t)(ok ? grow : 0) * K + k0 + kq;
            uint32_t dst = (uint32_t)__cvta_generic_to_shared(&As[s][r * APAD + kq]);
            cp16(dst, src, ok);
        }
        #pragma unroll
        for (int j = 0; j < 2; j++) {
            int i = tid + j * 256;
            int kr = i >> 5, cq = (i & 31) * 4;
            const float* src = W + (size_t)(k0 + kr) * FDIM + colBase + cq;
            uint32_t dst = (uint32_t)__cvta_generic_to_shared(&Bs[s][kr * BPAD + cq]);
            cp16(dst, src, 16);
        }
    };

    load_tiles(0, 0);
    cp_commit();
    if (nk > 1) { load_tiles(1, 16); }
    cp_commit();

    for (int kt = 0; kt < nk; kt++) {
        int cur = kt % NSTG;
        cp_wait<1>();
        __syncthreads();
        if (kt + 2 < nk) { load_tiles((kt + 2) % NSTG, (kt + 2) << 4); }
        cp_commit();

        #pragma unroll
        for (int kk = 0; kk < 16; kk += 8) {
            uint32_t af[4][4], bf[4][2];
            #pragma unroll
            for (int i = 0; i < 4; i++) {
                int r = mW + i * 16 + gid;
                af[i][0] = f2tf(As[cur][r * APAD + kk + tig]);
                af[i][1] = f2tf(As[cur][(r + 8) * APAD + kk + tig]);
                af[i][2] = f2tf(As[cur][r * APAD + kk + tig + 4]);
                af[i][3] = f2tf(As[cur][(r + 8) * APAD + kk + tig + 4]);
            }
            #pragma unroll
            for (int j = 0; j < 4; j++) {
                int c = nW + j * 8 + gid;
                bf[j][0] = f2tf(Bs[cur][(kk + tig) * BPAD + c]);
                bf[j][1] = f2tf(Bs[cur][(kk + tig + 4) * BPAD + c]);
            }
            #pragma unroll
            for (int i = 0; i < 4; i++)
                #pragma unroll
                for (int j = 0; j < 4; j++)
                    mma8(acc[i][j], af[i], bf[j]);
        }
        __syncthreads();
    }

    #pragma unroll
    for (int i = 0; i < 4; i++) {
        int r0 = rowBase + mW + i * 16 + gid;
        int r1 = r0 + 8;
        #pragma unroll
        for (int j = 0; j < 4; j++) {
            int c = colBase + nW + j * 8 + tig * 2;
            if (r0 < n) *(float2*)(C + (size_t)r0 * FDIM + c) =
                            make_float2(acc[i][j][0], acc[i][j][1]);
            if (r1 < n) *(float2*)(C + (size_t)r1 * FDIM + c) =
                            make_float2(acc[i][j][2], acc[i][j][3]);
        }
    }
}

// ======================= per-node attention dots (float4) ====================
__global__ void attn_kernel(const float* __restrict__ h,
                            const float* __restrict__ a_src,
                            const float* __restrict__ a_dst,
                            float* __restrict__ als, float* __restrict__ ald,
                            int H, int C) {
    int w = (blockIdx.x * blockDim.x + threadIdx.x) >> 5;
    int lane = threadIdx.x & 31;
    if (w >= NN * H) return;
    int n = w / H, hh = w - n * H;
    const float* hp  = h     + (size_t)n * FDIM + hh * C;
    const float* asp = a_src + hh * C;
    const float* adp = a_dst + hh * C;
    float s = 0.f, d = 0.f;
    for (int c = lane * 4; c < C; c += 128) {
        float4 v = *(const float4*)(hp + c);
        float4 a = *(const float4*)(asp + c);
        float4 b = *(const float4*)(adp + c);
        s += v.x * a.x + v.y * a.y + v.z * a.z + v.w * a.w;
        d += v.x * b.x + v.y * b.y + v.z * b.z + v.w * b.w;
    }
    #pragma unroll
    for (int o = 16; o > 0; o >>= 1) {
        s += __shfl_down_sync(0xffffffffu, s, o);
        d += __shfl_down_sync(0xffffffffu, d, o);
    }
    if (lane == 0) { als[w] = s; ald[w] = d; }
}

// ======================= fused single-pass softmax + aggregation =============
__device__ __forceinline__ float leaky(float l) {
    return (l > 0.f) ? l : SLOPE * l;
}

__global__ void gat_agg(const int* __restrict__ off, const int* __restrict__ csrc,
                        const float* __restrict__ h,
                        const float* __restrict__ als, const float* __restrict__ ald,
                        const float* __restrict__ bias,
                        float* __restrict__ out, int H, int C, int relu) {
    int dst = blockIdx.x;
    int w = threadIdx.x >> 5;
    int lane = threadIdx.x & 31;
    int cpw = C >> 7;
    int head = w / cpw;
    int chunk = w - head * cpw;

    int beg = off[dst], end = off[dst + 1];
    float ad = ald[dst * H + head];

    float4 acc = make_float4(0.f, 0.f, 0.f, 0.f);
    float sum = 0.f;
    int cbase = head * C + chunk * 128 + lane * 4;

    int e = beg;
    for (; e + 4 <= end; e += 4) {
        int s0 = csrc[e], s1 = csrc[e+1], s2 = csrc[e+2], s3 = csrc[e+3];
        float e0 = __expf(leaky(als[s0 * H + head] + ad));
        float e1 = __expf(leaky(als[s1 * H + head] + ad));
        float e2 = __expf(leaky(als[s2 * H + head] + ad));
        float e3 = __expf(leaky(als[s3 * H + head] + ad));
        float4 v0 = *(const float4*)(h + (size_t)s0 * FDIM + cbase);
        float4 v1 = *(const float4*)(h + (size_t)s1 * FDIM + cbase);
        float4 v2 = *(const float4*)(h + (size_t)s2 * FDIM + cbase);
        float4 v3 = *(const float4*)(h + (size_t)s3 * FDIM + cbase);
        sum += (e0 + e1) + (e2 + e3);
        acc.x += v0.x*e0 + v1.x*e1 + v2.x*e2 + v3.x*e3;
        acc.y += v0.y*e0 + v1.y*e1 + v2.y*e2 + v3.y*e3;
        acc.z += v0.z*e0 + v1.z*e1 + v2.z*e2 + v3.z*e3;
        acc.w += v0.w*e0 + v1.w*e1 + v2.w*e2 + v3.w*e3;
    }
    for (; e < end; e++) {
        int s = csrc[e];
        float e0 = __expf(leaky(als[s * H + head] + ad));
        float4 v = *(const float4*)(h + (size_t)s * FDIM + cbase);
        sum += e0;
        acc.x += v.x * e0; acc.y += v.y * e0;
        acc.z += v.z * e0; acc.w += v.w * e0;
    }

    float inv = 1.f / sum;
    float4 bv = *(const float4*)(bias + cbase);
    acc.x = acc.x * inv + bv.x;
    acc.y = acc.y * inv + bv.y;
    acc.z = acc.z * inv + bv.z;
    acc.w = acc.w * inv + bv.w;
    if (relu) {
        acc.x = fmaxf(acc.x, 0.f); acc.y = fmaxf(acc.y, 0.f);
        acc.z = fmaxf(acc.z, 0.f); acc.w = fmaxf(acc.w, 0.f);
    }
    *(float4*)(out + (size_t)dst * FDIM + cbase) = acc;
}

// ======================= host-side driver ====================================
static void run_layer(const float* A, int K, const float* W,
                      const float* a_src, const float* a_dst, const float* bias,
                      int H, int C,
                      const int* off, const int* csrc,
                      float* hbuf, float* aggout,
                      float* als, float* ald, int relu) {
    dim3 gg(FDIM / 128, (NN + 127) / 128);
    tf32gemm<<<gg, 256>>>(A, W, hbuf, NN, K);

    int warpsA = NN * H;
    attn_kernel<<<(warpsA * 32 + 255) / 256, 256>>>(hbuf, a_src, a_dst, als, ald, H, C);

    gat_agg<<<NN, 128>>>(off, csrc, hbuf, als, ald, bias, aggout, H, C, relu);
}

extern "C" void kernel_launch(void* const* d_in, const int* in_sizes, int n_in,
                              void* d_out, int out_size) {
    const float* x   = (const float*)d_in[0];
    const int*   ei  = (const int*)  d_in[1];
    const float* W1  = (const float*)d_in[2];
    const float* as1 = (const float*)d_in[3];
    const float* ad1 = (const float*)d_in[4];
    const float* b1  = (const float*)d_in[5];
    const float* W2  = (const float*)d_in[6];
    const float* as2 = (const float*)d_in[7];
    const float* ad2 = (const float*)d_in[8];
    const float* b2  = (const float*)d_in[9];
    const float* W3  = (const float*)d_in[10];
    const float* as3 = (const float*)d_in[11];
    const float* ad3 = (const float*)d_in[12];
    const float* b3  = (const float*)d_in[13];
    float* out = (float*)d_out;

    float *feat, *hbuf, *als, *ald;
    int *off, *pos, *csrc;
    cudaGetSymbolAddress((void**)&feat, g_feat);
    cudaGetSymbolAddress((void**)&hbuf, g_h);
    cudaGetSymbolAddress((void**)&als,  g_als);
    cudaGetSymbolAddress((void**)&ald,  g_ald);
    cudaGetSymbolAddress((void**)&off,  g_off);
    cudaGetSymbolAddress((void**)&pos,  g_pos);
    cudaGetSymbolAddress((void**)&csrc, g_csrc);

    // ---- build CSR (dst-sorted) ----
    zero_counts<<<(NN + 255) / 256, 256>>>(pos);
    count_deg<<<(ET / 4 + 255) / 256, 256>>>(ei, pos);
    scan_kernel<<<1, 1024>>>(pos, off, pos);
    scatter_edges<<<(ET / 4 + 255) / 256, 256>>>(ei, pos, csrc);

    // ---- 3 GAT layers ----
    run_layer(x,    128, W1, as1, ad1, b1, 4, 128, off, csrc, hbuf, feat, als, ald, 1);
    run_layer(feat, 512, W2, as2, ad2, b2, 4, 128, off, csrc, hbuf, feat, als, ald, 1);
    run_layer(feat, 512, W3, as3, ad3, b3, 1, 512, off, csrc, hbuf, out,  als, ald, 0);
}

// round 13
// speedup vs baseline: 1.1891x; 1.1821x over previous
#include <cuda_runtime.h>
#include <cuda_bf16.h>
#include <stdint.h>
#include <math.h>

#define NN 10000        // nodes
#define EE 320000       // raw edges
#define ET 330000       // edges + self loops
#define FDIM 512        // H*C for all layers
#define SLOPE 0.2f

// ---------------- scratch (static device globals) ----------------------------
__device__ float          g_feat[NN * FDIM];   // fp32 activations (GEMM A input)
__device__ __nv_bfloat16  g_hb  [NN * FDIM];   // h buffer bf16 (gather side)
__device__ float          g_als [NN * 4];
__device__ float          g_ald [NN * 4];
__device__ int            g_off [NN + 1];
__device__ int            g_pos [NN];
__device__ int            g_csrc[ET];

// ======================= CSR build (round-9 scalar versions) =================
__global__ void zero_counts(int* cnt) {
    int i = blockIdx.x * blockDim.x + threadIdx.x;
    if (i < NN) cnt[i] = 0;
}

__global__ void count_deg(const int* __restrict__ ei, int* __restrict__ cnt) {
    int e = blockIdx.x * blockDim.x + threadIdx.x;
    if (e >= ET) return;
    int d = (e < EE) ? ei[EE + e] : (e - EE);
    atomicAdd(&cnt[d], 1);
}

#define SCHUNK 10   // 1024 * 10 >= NN
__global__ void scan_kernel(const int* __restrict__ cnt,
                            int* __restrict__ off, int* __restrict__ pos) {
    __shared__ int part[1024];
    int t = threadIdx.x;
    int base = t * SCHUNK;
    int local[SCHUNK];
    int s = 0;
    #pragma unroll
    for (int i = 0; i < SCHUNK; i++) {
        int idx = base + i;
        local[i] = s;
        s += (idx < NN) ? cnt[idx] : 0;
    }
    part[t] = s;
    __syncthreads();
    for (int o = 1; o < 1024; o <<= 1) {
        int v = (t >= o) ? part[t - o] : 0;
        __syncthreads();
        part[t] += v;
        __syncthreads();
    }
    int prev = (t > 0) ? part[t - 1] : 0;
    #pragma unroll
    for (int i = 0; i < SCHUNK; i++) {
        int idx = base + i;
        if (idx < NN) {
            int o = prev + local[i];
            off[idx] = o;
            pos[idx] = o;
        }
    }
    if (t == 1023) off[NN] = part[1023];
}

__global__ void scatter_edges(const int* __restrict__ ei,
                              int* __restrict__ pos, int* __restrict__ csrc) {
    int e = blockIdx.x * blockDim.x + threadIdx.x;
    if (e >= ET) return;
    int s, d;
    if (e < EE) { s = ei[e]; d = ei[EE + e]; } else { s = d = e - EE; }
    int p = atomicAdd(&pos[d], 1);
    csrc[p] = s;
}

// ======================= tf32 tensor-core GEMM (cp.async 2-stage) ============
__device__ __forceinline__ uint32_t f2tf(float f) {
    uint32_t r; asm("cvt.rna.tf32.f32 %0, %1;" : "=r"(r) : "f"(f)); return r;
}

__device__ __forceinline__ void mma8(float* d, const uint32_t* a, const uint32_t* b) {
    asm volatile("mma.sync.aligned.m16n8k8.row.col.f32.tf32.tf32.f32 "
                 "{%0,%1,%2,%3},{%4,%5,%6,%7},{%8,%9},{%0,%1,%2,%3};"
                 : "+f"(d[0]), "+f"(d[1]), "+f"(d[2]), "+f"(d[3])
                 : "r"(a[0]), "r"(a[1]), "r"(a[2]), "r"(a[3]),
                   "r"(b[0]), "r"(b[1]));
}

__device__ __forceinline__ void cp16(uint32_t dst, const void* src, int bytes) {
    asm volatile("cp.async.cg.shared.global [%0], [%1], 16, %2;"
                 :: "r"(dst), "l"(src), "r"(bytes));
}
__device__ __forceinline__ void cp_commit() {
    asm volatile("cp.async.commit_group;");
}
template<int N> __device__ __forceinline__ void cp_wait() {
    asm volatile("cp.async.wait_group %0;" :: "n"(N));
}

#define APAD 20
#define BPAD 136

__global__ __launch_bounds__(256, 2)
void tf32gemm(const float* __restrict__ A, const float* __restrict__ W,
              __nv_bfloat16* __restrict__ C, int n, int K) {
    __shared__ float As[2][128 * APAD];
    __shared__ float Bs[2][16 * BPAD];

    int tid = threadIdx.x;
    int wid = tid >> 5, lane = tid & 31;
    int gid = lane >> 2, tig = lane & 3;
    int mW = (wid & 1) * 64;
    int nW = (wid >> 1) * 32;
    int rowBase = blockIdx.y * 128;
    int colBase = blockIdx.x * 128;

    float acc[4][4][4] = {};
    int nk = K >> 4;

    auto load_tiles = [&](int s, int k0) {
        #pragma unroll
        for (int j = 0; j < 2; j++) {
            int i = tid + j * 256;
            int r = i >> 2, kq = (i & 3) * 4;
            int grow = rowBase + r;
            int ok = (grow < n) ? 16 : 0;
            const float* src = A + (size_t)(ok ? grow : 0) * K + k0 + kq;
            uint32_t dst = (uint32_t)__cvta_generic_to_shared(&As[s][r * APAD + kq]);
            cp16(dst, src, ok);
        }
        #pragma unroll
        for (int j = 0; j < 2; j++) {
            int i = tid + j * 256;
            int kr = i >> 5, cq = (i & 31) * 4;
            const float* src = W + (size_t)(k0 + kr) * FDIM + colBase + cq;
            uint32_t dst = (uint32_t)__cvta_generic_to_shared(&Bs[s][kr * BPAD + cq]);
            cp16(dst, src, 16);
        }
    };

    load_tiles(0, 0);
    cp_commit();

    for (int kt = 0; kt < nk; kt++) {
        int cur = kt & 1;
        if (kt + 1 < nk) {
            load_tiles(cur ^ 1, (kt + 1) << 4);
            cp_commit();
            cp_wait<1>();
        } else {
            cp_wait<0>();
        }
        __syncthreads();

        #pragma unroll
        for (int kk = 0; kk < 16; kk += 8) {
            uint32_t af[4][4], bf[4][2];
            #pragma unroll
            for (int i = 0; i < 4; i++) {
                int r = mW + i * 16 + gid;
                af[i][0] = f2tf(As[cur][r * APAD + kk + tig]);
                af[i][1] = f2tf(As[cur][(r + 8) * APAD + kk + tig]);
                af[i][2] = f2tf(As[cur][r * APAD + kk + tig + 4]);
                af[i][3] = f2tf(As[cur][(r + 8) * APAD + kk + tig + 4]);
            }
            #pragma unroll
            for (int j = 0; j < 4; j++) {
                int c = nW + j * 8 + gid;
                bf[j][0] = f2tf(Bs[cur][(kk + tig) * BPAD + c]);
                bf[j][1] = f2tf(Bs[cur][(kk + tig + 4) * BPAD + c]);
            }
            #pragma unroll
            for (int i = 0; i < 4; i++)
                #pragma unroll
                for (int j = 0; j < 4; j++)
                    mma8(acc[i][j], af[i], bf[j]);
        }
        __syncthreads();
    }

    // epilogue: bf16 stores
    #pragma unroll
    for (int i = 0; i < 4; i++) {
        int r0 = rowBase + mW + i * 16 + gid;
        int r1 = r0 + 8;
        #pragma unroll
        for (int j = 0; j < 4; j++) {
            int c = colBase + nW + j * 8 + tig * 2;
            if (r0 < n) *(__nv_bfloat162*)(C + (size_t)r0 * FDIM + c) =
                __float22bfloat162_rn(make_float2(acc[i][j][0], acc[i][j][1]));
            if (r1 < n) *(__nv_bfloat162*)(C + (size_t)r1 * FDIM + c) =
                __float22bfloat162_rn(make_float2(acc[i][j][2], acc[i][j][3]));
        }
    }
}

// ======================= per-node attention dots (bf16 h, 16B loads) =========
__global__ void attn_kernel(const __nv_bfloat16* __restrict__ h,
                            const float* __restrict__ a_src,
                            const float* __restrict__ a_dst,
                            float* __restrict__ als, float* __restrict__ ald,
                            int H, int C) {
    int w = (blockIdx.x * blockDim.x + threadIdx.x) >> 5;
    int lane = threadIdx.x & 31;
    if (w >= NN * H) return;
    int n = w / H, hh = w - n * H;
    const __nv_bfloat16* hp = h + (size_t)n * FDIM + hh * C;
    const float* asp = a_src + hh * C;
    const float* adp = a_dst + hh * C;
    float s = 0.f, d = 0.f;
    for (int c = lane * 8; c < C; c += 256) {
        uint4 raw = *(const uint4*)(hp + c);     // 8 bf16 = 16B
        float2 f0 = __bfloat1622float2(*(__nv_bfloat162*)&raw.x);
        float2 f1 = __bfloat1622float2(*(__nv_bfloat162*)&raw.y);
        float2 f2 = __bfloat1622float2(*(__nv_bfloat162*)&raw.z);
        float2 f3 = __bfloat1622float2(*(__nv_bfloat162*)&raw.w);
        float4 a0 = *(const float4*)(asp + c);
        float4 a1 = *(const float4*)(asp + c + 4);
        float4 b0 = *(const float4*)(adp + c);
        float4 b1 = *(const float4*)(adp + c + 4);
        s += f0.x*a0.x + f0.y*a0.y + f1.x*a0.z + f1.y*a0.w
           + f2.x*a1.x + f2.y*a1.y + f3.x*a1.z + f3.y*a1.w;
        d += f0.x*b0.x + f0.y*b0.y + f1.x*b0.z + f1.y*b0.w
           + f2.x*b1.x + f2.y*b1.y + f3.x*b1.z + f3.y*b1.w;
    }
    #pragma unroll
    for (int o = 16; o > 0; o >>= 1) {
        s += __shfl_down_sync(0xffffffffu, s, o);
        d += __shfl_down_sync(0xffffffffu, d, o);
    }
    if (lane == 0) { als[w] = s; ald[w] = d; }
}

// ======================= fused single-pass softmax + aggregation =============
// 2 dsts per 128-thread block; 2 warps per dst; 8 bf16 channels per lane
// (one warp covers 256 channels -> 16B LDG per lane per edge).
__device__ __forceinline__ float leaky(float l) {
    return (l > 0.f) ? l : SLOPE * l;
}

__device__ __forceinline__ void bf8_fma(float* acc, uint4 raw, float e) {
    float2 f0 = __bfloat1622float2(*(__nv_bfloat162*)&raw.x);
    float2 f1 = __bfloat1622float2(*(__nv_bfloat162*)&raw.y);
    float2 f2 = __bfloat1622float2(*(__nv_bfloat162*)&raw.z);
    float2 f3 = __bfloat1622float2(*(__nv_bfloat162*)&raw.w);
    acc[0] += f0.x * e; acc[1] += f0.y * e;
    acc[2] += f1.x * e; acc[3] += f1.y * e;
    acc[4] += f2.x * e; acc[5] += f2.y * e;
    acc[6] += f3.x * e; acc[7] += f3.y * e;
}

__global__ void gat_agg(const int* __restrict__ off, const int* __restrict__ csrc,
                        const __nv_bfloat16* __restrict__ h,
                        const float* __restrict__ als, const float* __restrict__ ald,
                        const float* __restrict__ bias,
                        float* __restrict__ out, int H, int C, int relu) {
    int dst  = blockIdx.x * 2 + (threadIdx.x >> 6);
    if (dst >= NN) return;
    int wIn  = (threadIdx.x >> 5) & 1;     // warp within dst: 0 or 1
    int lane = threadIdx.x & 31;

    int ch0  = wIn * 256 + lane * 8;       // this lane's 8 channels
    int head = ch0 / C;                    // C=128 -> 0..3, C=512 -> 0
    float ad = ald[dst * H + head];

    int beg = off[dst], end = off[dst + 1];

    float acc[8] = {};
    float sum = 0.f;
    const __nv_bfloat16* hc = h + ch0;

    int e = beg;
    for (; e + 4 <= end; e += 4) {
        int s0 = csrc[e], s1 = csrc[e+1], s2 = csrc[e+2], s3 = csrc[e+3];
        float e0 = __expf(leaky(als[s0 * H + head] + ad));
        float e1 = __expf(leaky(als[s1 * H + head] + ad));
        float e2 = __expf(leaky(als[s2 * H + head] + ad));
        float e3 = __expf(leaky(als[s3 * H + head] + ad));
        uint4 r0 = *(const uint4*)(hc + (size_t)s0 * FDIM);
        uint4 r1 = *(const uint4*)(hc + (size_t)s1 * FDIM);
        uint4 r2 = *(const uint4*)(hc + (size_t)s2 * FDIM);
        uint4 r3 = *(const uint4*)(hc + (size_t)s3 * FDIM);
        sum += (e0 + e1) + (e2 + e3);
        bf8_fma(acc, r0, e0); bf8_fma(acc, r1, e1);
        bf8_fma(acc, r2, e2); bf8_fma(acc, r3, e3);
    }
    for (; e < end; e++) {
        int s = csrc[e];
        float e0 = __expf(leaky(als[s * H + head] + ad));
        uint4 r = *(const uint4*)(hc + (size_t)s * FDIM);
        sum += e0;
        bf8_fma(acc, r, e0);
    }

    float inv = 1.f / sum;
    float4 b0 = *(const float4*)(bias + ch0);
    float4 b1 = *(const float4*)(bias + ch0 + 4);
    float o0 = acc[0]*inv + b0.x, o1 = acc[1]*inv + b0.y;
    float o2 = acc[2]*inv + b0.z, o3 = acc[3]*inv + b0.w;
    float o4 = acc[4]*inv + b1.x, o5 = acc[5]*inv + b1.y;
    float o6 = acc[6]*inv + b1.z, o7 = acc[7]*inv + b1.w;
    if (relu) {
        o0 = fmaxf(o0, 0.f); o1 = fmaxf(o1, 0.f);
        o2 = fmaxf(o2, 0.f); o3 = fmaxf(o3, 0.f);
        o4 = fmaxf(o4, 0.f); o5 = fmaxf(o5, 0.f);
        o6 = fmaxf(o6, 0.f); o7 = fmaxf(o7, 0.f);
    }
    float* op = out + (size_t)dst * FDIM + ch0;
    *(float4*)op       = make_float4(o0, o1, o2, o3);
    *(float4*)(op + 4) = make_float4(o4, o5, o6, o7);
}

// ======================= host-side driver ====================================
static void run_layer(const float* A, int K, const float* W,
                      const float* a_src, const float* a_dst, const float* bias,
                      int H, int C,
                      const int* off, const int* csrc,
                      __nv_bfloat16* hbuf, float* aggout,
                      float* als, float* ald, int relu) {
    dim3 gg(FDIM / 128, (NN + 127) / 128);
    tf32gemm<<<gg, 256>>>(A, W, hbuf, NN, K);

    int warpsA = NN * H;
    attn_kernel<<<(warpsA * 32 + 255) / 256, 256>>>(hbuf, a_src, a_dst, als, ald, H, C);

    gat_agg<<<(NN + 1) / 2, 128>>>(off, csrc, hbuf, als, ald, bias, aggout, H, C, relu);
}

extern "C" void kernel_launch(void* const* d_in, const int* in_sizes, int n_in,
                              void* d_out, int out_size) {
    const float* x   = (const float*)d_in[0];
    const int*   ei  = (const int*)  d_in[1];
    const float* W1  = (const float*)d_in[2];
    const float* as1 = (const float*)d_in[3];
    const float* ad1 = (const float*)d_in[4];
    const float* b1  = (const float*)d_in[5];
    const float* W2  = (const float*)d_in[6];
    const float* as2 = (const float*)d_in[7];
    const float* ad2 = (const float*)d_in[8];
    const float* b2  = (const float*)d_in[9];
    const float* W3  = (const float*)d_in[10];
    const float* as3 = (const float*)d_in[11];
    const float* ad3 = (const float*)d_in[12];
    const float* b3  = (const float*)d_in[13];
    float* out = (float*)d_out;

    float *feat, *als, *ald;
    __nv_bfloat16* hbuf;
    int *off, *pos, *csrc;
    cudaGetSymbolAddress((void**)&feat, g_feat);
    cudaGetSymbolAddress((void**)&hbuf, g_hb);
    cudaGetSymbolAddress((void**)&als,  g_als);
    cudaGetSymbolAddress((void**)&ald,  g_ald);
    cudaGetSymbolAddress((void**)&off,  g_off);
    cudaGetSymbolAddress((void**)&pos,  g_pos);
    cudaGetSymbolAddress((void**)&csrc, g_csrc);

    // side stream + events, created once (outside capture: first call is the
    // uncaptured correctness run)
    static cudaStream_t s2 = 0;
    static cudaEvent_t evFork = 0, evJoin = 0;
    if (!s2) {
        cudaStreamCreate(&s2);
        cudaEventCreateWithFlags(&evFork, cudaEventDisableTiming);
        cudaEventCreateWithFlags(&evJoin, cudaEventDisableTiming);
    }

    // ---- fork: CSR build on s2, overlapped with layer-1 GEMM + attn ----
    cudaEventRecord(evFork, 0);
    cudaStreamWaitEvent(s2, evFork, 0);
    zero_counts  <<<(NN + 255) / 256, 256, 0, s2>>>(pos);
    count_deg    <<<(ET + 255) / 256, 256, 0, s2>>>(ei, pos);
    scan_kernel  <<<1, 1024, 0, s2>>>(pos, off, pos);
    scatter_edges<<<(ET + 255) / 256, 256, 0, s2>>>(ei, pos, csrc);
    cudaEventRecord(evJoin, s2);

    // ---- layer 1 GEMM + attn on default stream (independent of CSR) ----
    dim3 gg(FDIM / 128, (NN + 127) / 128);
    tf32gemm<<<gg, 256>>>(x, W1, hbuf, NN, 128);
    attn_kernel<<<(NN * 4 * 32 + 255) / 256, 256>>>(hbuf, as1, ad1, als, ald, 4, 128);

    // ---- join before first aggregation ----
    cudaStreamWaitEvent(0, evJoin, 0);
    gat_agg<<<(NN + 1) / 2, 128>>>(off, csrc, hbuf, als, ald, b1, feat, 4, 128, 1);

    // ---- layers 2, 3 ----
    run_layer(feat, 512, W2, as2, ad2, b2, 4, 128, off, csrc, hbuf, feat, als, ald, 1);
    run_layer(feat, 512, W3, as3, ad3, b3, 1, 512, off, csrc, hbuf, out,  als, ald, 0);
}

// round 14
// speedup vs baseline: 1.2418x; 1.0443x over previous
#include <cuda_runtime.h>
#include <cuda_bf16.h>
#include <stdint.h>
#include <math.h>

#define NN 10000        // nodes
#define EE 320000       // raw edges
#define ET 330000       // edges + self loops
#define FDIM 512        // H*C for all layers
#define SLOPE 0.2f

// ---------------- scratch (static device globals) ----------------------------
__device__ float          g_feat[NN * FDIM];   // fp32 activations (GEMM A input)
__device__ __nv_bfloat16  g_hb  [NN * FDIM];   // h buffer bf16 (gather side)
__device__ float          g_als [NN * 4];
__device__ float          g_ald [NN * 4];
__device__ int            g_off [NN + 1];
__device__ int            g_pos [NN];
__device__ int            g_csrc[ET];

// ======================= CSR build ===========================================
__global__ void zero_counts(int* cnt) {
    int i = blockIdx.x * blockDim.x + threadIdx.x;
    if (i < NN) cnt[i] = 0;
}

__global__ void count_deg(const int* __restrict__ ei, int* __restrict__ cnt) {
    int e = blockIdx.x * blockDim.x + threadIdx.x;
    if (e >= ET) return;
    int d = (e < EE) ? ei[EE + e] : (e - EE);
    atomicAdd(&cnt[d], 1);
}

#define SCHUNK 10   // 1024 * 10 >= NN
__global__ void scan_kernel(const int* __restrict__ cnt,
                            int* __restrict__ off, int* __restrict__ pos) {
    __shared__ int part[1024];
    int t = threadIdx.x;
    int base = t * SCHUNK;
    int local[SCHUNK];
    int s = 0;
    #pragma unroll
    for (int i = 0; i < SCHUNK; i++) {
        int idx = base + i;
        local[i] = s;
        s += (idx < NN) ? cnt[idx] : 0;
    }
    part[t] = s;
    __syncthreads();
    for (int o = 1; o < 1024; o <<= 1) {
        int v = (t >= o) ? part[t - o] : 0;
        __syncthreads();
        part[t] += v;
        __syncthreads();
    }
    int prev = (t > 0) ? part[t - 1] : 0;
    #pragma unroll
    for (int i = 0; i < SCHUNK; i++) {
        int idx = base + i;
        if (idx < NN) {
            int o = prev + local[i];
            off[idx] = o;
            pos[idx] = o;
        }
    }
    if (t == 1023) off[NN] = part[1023];
}

__global__ void scatter_edges(const int* __restrict__ ei,
                              int* __restrict__ pos, int* __restrict__ csrc) {
    int e = blockIdx.x * blockDim.x + threadIdx.x;
    if (e >= ET) return;
    int s, d;
    if (e < EE) { s = ei[e]; d = ei[EE + e]; } else { s = d = e - EE; }
    int p = atomicAdd(&pos[d], 1);
    csrc[p] = s;
}

// ======================= attn accumulator zero ===============================
__global__ void zero_attn(float* __restrict__ als, float* __restrict__ ald) {
    int i = blockIdx.x * blockDim.x + threadIdx.x;
    if (i < NN * 4) { als[i] = 0.f; ald[i] = 0.f; }
}

// ======================= tf32 GEMM (BM=64, fused attn epilogue) ==============
__device__ __forceinline__ uint32_t f2tf(float f) {
    uint32_t r; asm("cvt.rna.tf32.f32 %0, %1;" : "=r"(r) : "f"(f)); return r;
}

__device__ __forceinline__ void mma8(float* d, const uint32_t* a, const uint32_t* b) {
    asm volatile("mma.sync.aligned.m16n8k8.row.col.f32.tf32.tf32.f32 "
                 "{%0,%1,%2,%3},{%4,%5,%6,%7},{%8,%9},{%0,%1,%2,%3};"
                 : "+f"(d[0]), "+f"(d[1]), "+f"(d[2]), "+f"(d[3])
                 : "r"(a[0]), "r"(a[1]), "r"(a[2]), "r"(a[3]),
                   "r"(b[0]), "r"(b[1]));
}

__device__ __forceinline__ void cp16(uint32_t dst, const void* src, int bytes) {
    asm volatile("cp.async.cg.shared.global [%0], [%1], 16, %2;"
                 :: "r"(dst), "l"(src), "r"(bytes));
}
__device__ __forceinline__ void cp_commit() {
    asm volatile("cp.async.commit_group;");
}
template<int N> __device__ __forceinline__ void cp_wait() {
    asm volatile("cp.async.wait_group %0;" :: "n"(N));
}

#define APAD 20
#define BPAD 136

__global__ __launch_bounds__(256, 3)
void tf32gemm(const float* __restrict__ A, const float* __restrict__ W,
              __nv_bfloat16* __restrict__ C, int n, int K,
              const float* __restrict__ a_src, const float* __restrict__ a_dst,
              float* __restrict__ als, float* __restrict__ ald, int H) {
    __shared__ float As[2][64 * APAD];
    __shared__ float Bs[2][16 * BPAD];

    int tid = threadIdx.x;
    int wid = tid >> 5, lane = tid & 31;
    int gid = lane >> 2, tig = lane & 3;
    int mW = (wid & 1) * 32;          // warp m offset (BM=64)
    int nW = (wid >> 1) * 32;         // warp n offset
    int rowBase = blockIdx.y * 64;
    int colBase = blockIdx.x * 128;

    float acc[2][4][4] = {};
    int nk = K >> 4;

    auto load_tiles = [&](int s, int k0) {
        {   // A tile: 64 rows x 16 k = 256 float4, 1 per thread
            int r = tid >> 2, kq = (tid & 3) * 4;
            int grow = rowBase + r;
            int ok = (grow < n) ? 16 : 0;
            const float* src = A + (size_t)(ok ? grow : 0) * K + k0 + kq;
            uint32_t dst = (uint32_t)__cvta_generic_to_shared(&As[s][r * APAD + kq]);
            cp16(dst, src, ok);
        }
        #pragma unroll
        for (int j = 0; j < 2; j++) {   // B tile: 16 x 128 = 512 float4, 2/thread
            int i = tid + j * 256;
            int kr = i >> 5, cq = (i & 31) * 4;
            const float* src = W + (size_t)(k0 + kr) * FDIM + colBase + cq;
            uint32_t dst = (uint32_t)__cvta_generic_to_shared(&Bs[s][kr * BPAD + cq]);
            cp16(dst, src, 16);
        }
    };

    load_tiles(0, 0);
    cp_commit();

    for (int kt = 0; kt < nk; kt++) {
        int cur = kt & 1;
        if (kt + 1 < nk) {
            load_tiles(cur ^ 1, (kt + 1) << 4);
            cp_commit();
            cp_wait<1>();
        } else {
            cp_wait<0>();
        }
        __syncthreads();

        #pragma unroll
        for (int kk = 0; kk < 16; kk += 8) {
            uint32_t af[2][4], bf[4][2];
            #pragma unroll
            for (int i = 0; i < 2; i++) {
                int r = mW + i * 16 + gid;
                af[i][0] = f2tf(As[cur][r * APAD + kk + tig]);
                af[i][1] = f2tf(As[cur][(r + 8) * APAD + kk + tig]);
                af[i][2] = f2tf(As[cur][r * APAD + kk + tig + 4]);
                af[i][3] = f2tf(As[cur][(r + 8) * APAD + kk + tig + 4]);
            }
            #pragma unroll
            for (int j = 0; j < 4; j++) {
                int c = nW + j * 8 + gid;
                bf[j][0] = f2tf(Bs[cur][(kk + tig) * BPAD + c]);
                bf[j][1] = f2tf(Bs[cur][(kk + tig + 4) * BPAD + c]);
            }
            #pragma unroll
            for (int i = 0; i < 2; i++)
                #pragma unroll
                for (int j = 0; j < 4; j++)
                    mma8(acc[i][j], af[i], bf[j]);
        }
        __syncthreads();
    }

    // ---- epilogue: bf16 stores + fused attention dot-products ----
    int head = (colBase * H) / FDIM;   // block columns lie in exactly one head
    #pragma unroll
    for (int i = 0; i < 2; i++) {
        int r0 = rowBase + mW + i * 16 + gid;
        int r1 = r0 + 8;
        float s0 = 0.f, d0 = 0.f, s1 = 0.f, d1 = 0.f;
        #pragma unroll
        for (int j = 0; j < 4; j++) {
            int c = colBase + nW + j * 8 + tig * 2;
            float2 av = *(const float2*)(a_src + c);
            float2 dv = *(const float2*)(a_dst + c);
            if (r0 < n) *(__nv_bfloat162*)(C + (size_t)r0 * FDIM + c) =
                __float22bfloat162_rn(make_float2(acc[i][j][0], acc[i][j][1]));
            if (r1 < n) *(__nv_bfloat162*)(C + (size_t)r1 * FDIM + c) =
                __float22bfloat162_rn(make_float2(acc[i][j][2], acc[i][j][3]));
            s0 += acc[i][j][0] * av.x + acc[i][j][1] * av.y;
            d0 += acc[i][j][0] * dv.x + acc[i][j][1] * dv.y;
            s1 += acc[i][j][2] * av.x + acc[i][j][3] * av.y;
            d1 += acc[i][j][2] * dv.x + acc[i][j][3] * dv.y;
        }
        // reduce over the 4 tig lanes of this quad (lane = gid*4 + tig)
        #pragma unroll
        for (int o = 1; o < 4; o <<= 1) {
            s0 += __shfl_xor_sync(0xffffffffu, s0, o);
            d0 += __shfl_xor_sync(0xffffffffu, d0, o);
            s1 += __shfl_xor_sync(0xffffffffu, s1, o);
            d1 += __shfl_xor_sync(0xffffffffu, d1, o);
        }
        if (tig == 0) {
            if (r0 < n) { atomicAdd(&als[r0 * H + head], s0);
                          atomicAdd(&ald[r0 * H + head], d0); }
            if (r1 < n) { atomicAdd(&als[r1 * H + head], s1);
                          atomicAdd(&ald[r1 * H + head], d1); }
        }
    }
}

// ======================= fused single-pass softmax + aggregation =============
__device__ __forceinline__ float leaky(float l) {
    return (l > 0.f) ? l : SLOPE * l;
}

__device__ __forceinline__ void bf8_fma(float* acc, uint4 raw, float e) {
    float2 f0 = __bfloat1622float2(*(__nv_bfloat162*)&raw.x);
    float2 f1 = __bfloat1622float2(*(__nv_bfloat162*)&raw.y);
    float2 f2 = __bfloat1622float2(*(__nv_bfloat162*)&raw.z);
    float2 f3 = __bfloat1622float2(*(__nv_bfloat162*)&raw.w);
    acc[0] += f0.x * e; acc[1] += f0.y * e;
    acc[2] += f1.x * e; acc[3] += f1.y * e;
    acc[4] += f2.x * e; acc[5] += f2.y * e;
    acc[6] += f3.x * e; acc[7] += f3.y * e;
}

__global__ void gat_agg(const int* __restrict__ off, const int* __restrict__ csrc,
                        const __nv_bfloat16* __restrict__ h,
                        const float* __restrict__ als, const float* __restrict__ ald,
                        const float* __restrict__ bias,
                        float* __restrict__ out, int H, int C, int relu) {
    int dst  = blockIdx.x * 2 + (threadIdx.x >> 6);
    if (dst >= NN) return;
    int wIn  = (threadIdx.x >> 5) & 1;
    int lane = threadIdx.x & 31;

    int ch0  = wIn * 256 + lane * 8;
    int head = ch0 / C;
    float ad = ald[dst * H + head];

    int beg = off[dst], end = off[dst + 1];

    float acc[8] = {};
    float sum = 0.f;
    const __nv_bfloat16* hc = h + ch0;

    int e = beg;
    for (; e + 4 <= end; e += 4) {
        int s0 = csrc[e], s1 = csrc[e+1], s2 = csrc[e+2], s3 = csrc[e+3];
        float e0 = __expf(leaky(als[s0 * H + head] + ad));
        float e1 = __expf(leaky(als[s1 * H + head] + ad));
        float e2 = __expf(leaky(als[s2 * H + head] + ad));
        float e3 = __expf(leaky(als[s3 * H + head] + ad));
        uint4 r0 = *(const uint4*)(hc + (size_t)s0 * FDIM);
        uint4 r1 = *(const uint4*)(hc + (size_t)s1 * FDIM);
        uint4 r2 = *(const uint4*)(hc + (size_t)s2 * FDIM);
        uint4 r3 = *(const uint4*)(hc + (size_t)s3 * FDIM);
        sum += (e0 + e1) + (e2 + e3);
        bf8_fma(acc, r0, e0); bf8_fma(acc, r1, e1);
        bf8_fma(acc, r2, e2); bf8_fma(acc, r3, e3);
    }
    for (; e < end; e++) {
        int s = csrc[e];
        float e0 = __expf(leaky(als[s * H + head] + ad));
        uint4 r = *(const uint4*)(hc + (size_t)s * FDIM);
        sum += e0;
        bf8_fma(acc, r, e0);
    }

    float inv = 1.f / sum;
    float4 b0 = *(const float4*)(bias + ch0);
    float4 b1 = *(const float4*)(bias + ch0 + 4);
    float o0 = acc[0]*inv + b0.x, o1 = acc[1]*inv + b0.y;
    float o2 = acc[2]*inv + b0.z, o3 = acc[3]*inv + b0.w;
    float o4 = acc[4]*inv + b1.x, o5 = acc[5]*inv + b1.y;
    float o6 = acc[6]*inv + b1.z, o7 = acc[7]*inv + b1.w;
    if (relu) {
        o0 = fmaxf(o0, 0.f); o1 = fmaxf(o1, 0.f);
        o2 = fmaxf(o2, 0.f); o3 = fmaxf(o3, 0.f);
        o4 = fmaxf(o4, 0.f); o5 = fmaxf(o5, 0.f);
        o6 = fmaxf(o6, 0.f); o7 = fmaxf(o7, 0.f);
    }
    float* op = out + (size_t)dst * FDIM + ch0;
    *(float4*)op       = make_float4(o0, o1, o2, o3);
    *(float4*)(op + 4) = make_float4(o4, o5, o6, o7);
}

// ======================= host-side driver ====================================
static void run_layer(const float* A, int K, const float* W,
                      const float* a_src, const float* a_dst, const float* bias,
                      int H, int C,
                      const int* off, const int* csrc,
                      __nv_bfloat16* hbuf, float* aggout,
                      float* als, float* ald, int relu) {
    zero_attn<<<(NN * 4 + 255) / 256, 256>>>(als, ald);
    dim3 gg(FDIM / 128, (NN + 63) / 64);
    tf32gemm<<<gg, 256>>>(A, W, hbuf, NN, K, a_src, a_dst, als, ald, H);
    gat_agg<<<(NN + 1) / 2, 128>>>(off, csrc, hbuf, als, ald, bias, aggout, H, C, relu);
}

extern "C" void kernel_launch(void* const* d_in, const int* in_sizes, int n_in,
                              void* d_out, int out_size) {
    const float* x   = (const float*)d_in[0];
    const int*   ei  = (const int*)  d_in[1];
    const float* W1  = (const float*)d_in[2];
    const float* as1 = (const float*)d_in[3];
    const float* ad1 = (const float*)d_in[4];
    const float* b1  = (const float*)d_in[5];
    const float* W2  = (const float*)d_in[6];
    const float* as2 = (const float*)d_in[7];
    const float* ad2 = (const float*)d_in[8];
    const float* b2  = (const float*)d_in[9];
    const float* W3  = (const float*)d_in[10];
    const float* as3 = (const float*)d_in[11];
    const float* ad3 = (const float*)d_in[12];
    const float* b3  = (const float*)d_in[13];
    float* out = (float*)d_out;

    float *feat, *als, *ald;
    __nv_bfloat16* hbuf;
    int *off, *pos, *csrc;
    cudaGetSymbolAddress((void**)&feat, g_feat);
    cudaGetSymbolAddress((void**)&hbuf, g_hb);
    cudaGetSymbolAddress((void**)&als,  g_als);
    cudaGetSymbolAddress((void**)&ald,  g_ald);
    cudaGetSymbolAddress((void**)&off,  g_off);
    cudaGetSymbolAddress((void**)&pos,  g_pos);
    cudaGetSymbolAddress((void**)&csrc, g_csrc);

    static cudaStream_t s2 = 0;
    static cudaEvent_t evFork = 0, evJoin = 0;
    if (!s2) {
        cudaStreamCreate(&s2);
        cudaEventCreateWithFlags(&evFork, cudaEventDisableTiming);
        cudaEventCreateWithFlags(&evJoin, cudaEventDisableTiming);
    }

    // ---- fork: CSR build on s2, overlapped with layer-1 GEMM ----
    cudaEventRecord(evFork, 0);
    cudaStreamWaitEvent(s2, evFork, 0);
    zero_counts  <<<(NN + 255) / 256, 256, 0, s2>>>(pos);
    count_deg    <<<(ET + 255) / 256, 256, 0, s2>>>(ei, pos);
    scan_kernel  <<<1, 1024, 0, s2>>>(pos, off, pos);
    scatter_edges<<<(ET + 255) / 256, 256, 0, s2>>>(ei, pos, csrc);
    cudaEventRecord(evJoin, s2);

    // ---- layer 1 GEMM (+fused attn) on default stream ----
    zero_attn<<<(NN * 4 + 255) / 256, 256>>>(als, ald);
    dim3 gg(FDIM / 128, (NN + 63) / 64);
    tf32gemm<<<gg, 256>>>(x, W1, hbuf, NN, 128, as1, ad1, als, ald, 4);

    // ---- join before first aggregation ----
    cudaStreamWaitEvent(0, evJoin, 0);
    gat_agg<<<(NN + 1) / 2, 128>>>(off, csrc, hbuf, als, ald, b1, feat, 4, 128, 1);

    // ---- layers 2, 3 ----
    run_layer(feat, 512, W2, as2, ad2, b2, 4, 128, off, csrc, hbuf, feat, als, ald, 1);
    run_layer(feat, 512, W3, as3, ad3, b3, 1, 512, off, csrc, hbuf, out,  als, ald, 0);
}

// round 15
// speedup vs baseline: 1.2579x; 1.0129x over previous
#include <cuda_runtime.h>
#include <cuda_bf16.h>
#include <stdint.h>
#include <math.h>

#define NN 10000        // nodes
#define EE 320000       // raw edges
#define ET 330000       // edges + self loops
#define FDIM 512        // H*C for all layers
#define SLOPE 0.2f

// ---------------- scratch (static device globals) ----------------------------
__device__ float          g_feat[NN * FDIM];   // fp32 activations (GEMM A input)
__device__ __nv_bfloat16  g_hb  [NN * FDIM];   // h buffer bf16 (gather side)
__device__ float          g_als [NN * 4];
__device__ float          g_ald [NN * 4];
__device__ float          g_alsP[4 * NN];      // per-colblock partials (H=1)
__device__ float          g_aldP[4 * NN];
__device__ int            g_off [NN + 1];
__device__ int            g_pos [NN];
__device__ int            g_csrc[ET];

// ======================= CSR build ===========================================
__global__ void zero_counts(int* cnt) {
    int i = blockIdx.x * blockDim.x + threadIdx.x;
    if (i < NN) cnt[i] = 0;
}

__global__ void count_deg(const int* __restrict__ ei, int* __restrict__ cnt) {
    int e = blockIdx.x * blockDim.x + threadIdx.x;
    if (e >= ET) return;
    int d = (e < EE) ? ei[EE + e] : (e - EE);
    atomicAdd(&cnt[d], 1);
}

#define SCHUNK 10   // 1024 * 10 >= NN
__global__ void scan_kernel(const int* __restrict__ cnt,
                            int* __restrict__ off, int* __restrict__ pos) {
    __shared__ int part[1024];
    int t = threadIdx.x;
    int base = t * SCHUNK;
    int local[SCHUNK];
    int s = 0;
    #pragma unroll
    for (int i = 0; i < SCHUNK; i++) {
        int idx = base + i;
        local[i] = s;
        s += (idx < NN) ? cnt[idx] : 0;
    }
    part[t] = s;
    __syncthreads();
    for (int o = 1; o < 1024; o <<= 1) {
        int v = (t >= o) ? part[t - o] : 0;
        __syncthreads();
        part[t] += v;
        __syncthreads();
    }
    int prev = (t > 0) ? part[t - 1] : 0;
    #pragma unroll
    for (int i = 0; i < SCHUNK; i++) {
        int idx = base + i;
        if (idx < NN) {
            int o = prev + local[i];
            off[idx] = o;
            pos[idx] = o;
        }
    }
    if (t == 1023) off[NN] = part[1023];
}

__global__ void scatter_edges(const int* __restrict__ ei,
                              int* __restrict__ pos, int* __restrict__ csrc) {
    int e = blockIdx.x * blockDim.x + threadIdx.x;
    if (e >= ET) return;
    int s, d;
    if (e < EE) { s = ei[e]; d = ei[EE + e]; } else { s = d = e - EE; }
    int p = atomicAdd(&pos[d], 1);
    csrc[p] = s;
}

// ======================= combine per-colblock attn partials (H=1) ============
__global__ void combine_attn(const float* __restrict__ alsP,
                             const float* __restrict__ aldP,
                             float* __restrict__ als, float* __restrict__ ald) {
    int i = blockIdx.x * blockDim.x + threadIdx.x;
    if (i >= NN) return;
    als[i] = alsP[i] + alsP[NN + i] + alsP[2 * NN + i] + alsP[3 * NN + i];
    ald[i] = aldP[i] + aldP[NN + i] + aldP[2 * NN + i] + aldP[3 * NN + i];
}

// ======================= tf32 GEMM (BM=64, fused attn epilogue) ==============
__device__ __forceinline__ uint32_t f2tf(float f) {
    uint32_t r; asm("cvt.rna.tf32.f32 %0, %1;" : "=r"(r) : "f"(f)); return r;
}

__device__ __forceinline__ void mma8(float* d, const uint32_t* a, const uint32_t* b) {
    asm volatile("mma.sync.aligned.m16n8k8.row.col.f32.tf32.tf32.f32 "
                 "{%0,%1,%2,%3},{%4,%5,%6,%7},{%8,%9},{%0,%1,%2,%3};"
                 : "+f"(d[0]), "+f"(d[1]), "+f"(d[2]), "+f"(d[3])
                 : "r"(a[0]), "r"(a[1]), "r"(a[2]), "r"(a[3]),
                   "r"(b[0]), "r"(b[1]));
}

__device__ __forceinline__ void cp16(uint32_t dst, const void* src, int bytes) {
    asm volatile("cp.async.cg.shared.global [%0], [%1], 16, %2;"
                 :: "r"(dst), "l"(src), "r"(bytes));
}
__device__ __forceinline__ void cp_commit() {
    asm volatile("cp.async.commit_group;");
}
template<int N> __device__ __forceinline__ void cp_wait() {
    asm volatile("cp.async.wait_group %0;" :: "n"(N));
}

#define APAD 20
#define BPAD 136

__global__ __launch_bounds__(256, 3)
void tf32gemm(const float* __restrict__ A, const float* __restrict__ W,
              __nv_bfloat16* __restrict__ C, int n, int K,
              const float* __restrict__ a_src, const float* __restrict__ a_dst,
              float* __restrict__ als, float* __restrict__ ald,
              float* __restrict__ alsP, float* __restrict__ aldP, int H) {
    __shared__ float As[2][64 * APAD];
    __shared__ float Bs[2][16 * BPAD];
    __shared__ float sRed[4][64][2];   // [nW-group][local row][s/d]

    int tid = threadIdx.x;
    int wid = tid >> 5, lane = tid & 31;
    int gid = lane >> 2, tig = lane & 3;
    int mW = (wid & 1) * 32;          // warp m offset (BM=64)
    int nW = (wid >> 1) * 32;         // warp n offset
    int nWg = wid >> 1;
    int rowBase = blockIdx.y * 64;
    int colBase = blockIdx.x * 128;

    float acc[2][4][4] = {};
    int nk = K >> 4;

    auto load_tiles = [&](int s, int k0) {
        {   // A tile: 64 rows x 16 k = 256 float4, 1 per thread
            int r = tid >> 2, kq = (tid & 3) * 4;
            int grow = rowBase + r;
            int ok = (grow < n) ? 16 : 0;
            const float* src = A + (size_t)(ok ? grow : 0) * K + k0 + kq;
            uint32_t dst = (uint32_t)__cvta_generic_to_shared(&As[s][r * APAD + kq]);
            cp16(dst, src, ok);
        }
        #pragma unroll
        for (int j = 0; j < 2; j++) {   // B tile: 16 x 128 = 512 float4, 2/thread
            int i = tid + j * 256;
            int kr = i >> 5, cq = (i & 31) * 4;
            const float* src = W + (size_t)(k0 + kr) * FDIM + colBase + cq;
            uint32_t dst = (uint32_t)__cvta_generic_to_shared(&Bs[s][kr * BPAD + cq]);
            cp16(dst, src, 16);
        }
    };

    load_tiles(0, 0);
    cp_commit();

    for (int kt = 0; kt < nk; kt++) {
        int cur = kt & 1;
        if (kt + 1 < nk) {
            load_tiles(cur ^ 1, (kt + 1) << 4);
            cp_commit();
            cp_wait<1>();
        } else {
            cp_wait<0>();
        }
        __syncthreads();

        #pragma unroll
        for (int kk = 0; kk < 16; kk += 8) {
            uint32_t af[2][4], bf[4][2];
            #pragma unroll
            for (int i = 0; i < 2; i++) {
                int r = mW + i * 16 + gid;
                af[i][0] = f2tf(As[cur][r * APAD + kk + tig]);
                af[i][1] = f2tf(As[cur][(r + 8) * APAD + kk + tig]);
                af[i][2] = f2tf(As[cur][r * APAD + kk + tig + 4]);
                af[i][3] = f2tf(As[cur][(r + 8) * APAD + kk + tig + 4]);
            }
            #pragma unroll
            for (int j = 0; j < 4; j++) {
                int c = nW + j * 8 + gid;
                bf[j][0] = f2tf(Bs[cur][(kk + tig) * BPAD + c]);
                bf[j][1] = f2tf(Bs[cur][(kk + tig + 4) * BPAD + c]);
            }
            #pragma unroll
            for (int i = 0; i < 2; i++)
                #pragma unroll
                for (int j = 0; j < 4; j++)
                    mma8(acc[i][j], af[i], bf[j]);
        }
        __syncthreads();
    }

    // ---- epilogue: bf16 stores + fused attention dot-products ----
    int head = (colBase * H) / FDIM;   // block columns lie in exactly one head
    #pragma unroll
    for (int i = 0; i < 2; i++) {
        int r0 = rowBase + mW + i * 16 + gid;
        int r1 = r0 + 8;
        float s0 = 0.f, d0 = 0.f, s1 = 0.f, d1 = 0.f;
        #pragma unroll
        for (int j = 0; j < 4; j++) {
            int c = colBase + nW + j * 8 + tig * 2;
            float2 av = *(const float2*)(a_src + c);
            float2 dv = *(const float2*)(a_dst + c);
            if (r0 < n) *(__nv_bfloat162*)(C + (size_t)r0 * FDIM + c) =
                __float22bfloat162_rn(make_float2(acc[i][j][0], acc[i][j][1]));
            if (r1 < n) *(__nv_bfloat162*)(C + (size_t)r1 * FDIM + c) =
                __float22bfloat162_rn(make_float2(acc[i][j][2], acc[i][j][3]));
            s0 += acc[i][j][0] * av.x + acc[i][j][1] * av.y;
            d0 += acc[i][j][0] * dv.x + acc[i][j][1] * dv.y;
            s1 += acc[i][j][2] * av.x + acc[i][j][3] * av.y;
            d1 += acc[i][j][2] * dv.x + acc[i][j][3] * dv.y;
        }
        #pragma unroll
        for (int o = 1; o < 4; o <<= 1) {
            s0 += __shfl_xor_sync(0xffffffffu, s0, o);
            d0 += __shfl_xor_sync(0xffffffffu, d0, o);
            s1 += __shfl_xor_sync(0xffffffffu, s1, o);
            d1 += __shfl_xor_sync(0xffffffffu, d1, o);
        }
        if (tig == 0) {
            int lr = mW + i * 16 + gid;
            sRed[nWg][lr][0] = s0;     sRed[nWg][lr][1] = d0;
            sRed[nWg][lr + 8][0] = s1; sRed[nWg][lr + 8][1] = d1;
        }
    }
    __syncthreads();
    if (tid < 64) {
        float ssum = sRed[0][tid][0] + sRed[1][tid][0]
                   + sRed[2][tid][0] + sRed[3][tid][0];
        float dsum = sRed[0][tid][1] + sRed[1][tid][1]
                   + sRed[2][tid][1] + sRed[3][tid][1];
        int grow = rowBase + tid;
        if (grow < n) {
            if (H == 4) {
                als[grow * 4 + head] = ssum;
                ald[grow * 4 + head] = dsum;
            } else {
                alsP[blockIdx.x * NN + grow] = ssum;
                aldP[blockIdx.x * NN + grow] = dsum;
            }
        }
    }
}

// ======================= fused single-pass softmax + aggregation =============
// 1 warp per dst; 16 bf16 channels per lane (2x LDG.128 per edge); 8 dsts/block.
__device__ __forceinline__ float leaky(float l) {
    return (l > 0.f) ? l : SLOPE * l;
}

__device__ __forceinline__ void bf8_fma(float* acc, uint4 raw, float e) {
    float2 f0 = __bfloat1622float2(*(__nv_bfloat162*)&raw.x);
    float2 f1 = __bfloat1622float2(*(__nv_bfloat162*)&raw.y);
    float2 f2 = __bfloat1622float2(*(__nv_bfloat162*)&raw.z);
    float2 f3 = __bfloat1622float2(*(__nv_bfloat162*)&raw.w);
    acc[0] += f0.x * e; acc[1] += f0.y * e;
    acc[2] += f1.x * e; acc[3] += f1.y * e;
    acc[4] += f2.x * e; acc[5] += f2.y * e;
    acc[6] += f3.x * e; acc[7] += f3.y * e;
}

__global__ void gat_agg(const int* __restrict__ off, const int* __restrict__ csrc,
                        const __nv_bfloat16* __restrict__ h,
                        const float* __restrict__ als, const float* __restrict__ ald,
                        const float* __restrict__ bias,
                        float* __restrict__ out, int H, int C, int relu) {
    int dst  = blockIdx.x * 8 + (threadIdx.x >> 5);
    if (dst >= NN) return;
    int lane = threadIdx.x & 31;

    int ch0  = lane * 16;              // this lane's 16 channels
    int head = ch0 / C;                // C=128 -> lane/8, C=512 -> 0
    float ad = ald[dst * H + head];

    int beg = off[dst], end = off[dst + 1];

    float acc[16] = {};
    float sum = 0.f;
    const __nv_bfloat16* hc = h + ch0;

    int e = beg;
    for (; e + 2 <= end; e += 2) {
        int s0 = csrc[e], s1 = csrc[e + 1];
        float e0 = __expf(leaky(als[s0 * H + head] + ad));
        float e1 = __expf(leaky(als[s1 * H + head] + ad));
        const __nv_bfloat16* p0 = hc + (size_t)s0 * FDIM;
        const __nv_bfloat16* p1 = hc + (size_t)s1 * FDIM;
        uint4 r00 = *(const uint4*)p0;
        uint4 r01 = *(const uint4*)(p0 + 8);
        uint4 r10 = *(const uint4*)p1;
        uint4 r11 = *(const uint4*)(p1 + 8);
        sum += e0 + e1;
        bf8_fma(acc,     r00, e0); bf8_fma(acc + 8, r01, e0);
        bf8_fma(acc,     r10, e1); bf8_fma(acc + 8, r11, e1);
    }
    if (e < end) {
        int s = csrc[e];
        float e0 = __expf(leaky(als[s * H + head] + ad));
        const __nv_bfloat16* p = hc + (size_t)s * FDIM;
        uint4 r0 = *(const uint4*)p;
        uint4 r1 = *(const uint4*)(p + 8);
        sum += e0;
        bf8_fma(acc, r0, e0); bf8_fma(acc + 8, r1, e0);
    }

    float inv = 1.f / sum;
    float* op = out + (size_t)dst * FDIM + ch0;
    #pragma unroll
    for (int q = 0; q < 4; q++) {
        float4 bv = *(const float4*)(bias + ch0 + q * 4);
        float o0 = acc[q*4+0] * inv + bv.x;
        float o1 = acc[q*4+1] * inv + bv.y;
        float o2 = acc[q*4+2] * inv + bv.z;
        float o3 = acc[q*4+3] * inv + bv.w;
        if (relu) {
            o0 = fmaxf(o0, 0.f); o1 = fmaxf(o1, 0.f);
            o2 = fmaxf(o2, 0.f); o3 = fmaxf(o3, 0.f);
        }
        *(float4*)(op + q * 4) = make_float4(o0, o1, o2, o3);
    }
}

// ======================= host-side driver ====================================
extern "C" void kernel_launch(void* const* d_in, const int* in_sizes, int n_in,
                              void* d_out, int out_size) {
    const float* x   = (const float*)d_in[0];
    const int*   ei  = (const int*)  d_in[1];
    const float* W1  = (const float*)d_in[2];
    const float* as1 = (const float*)d_in[3];
    const float* ad1 = (const float*)d_in[4];
    const float* b1  = (const float*)d_in[5];
    const float* W2  = (const float*)d_in[6];
    const float* as2 = (const float*)d_in[7];
    const float* ad2 = (const float*)d_in[8];
    const float* b2  = (const float*)d_in[9];
    const float* W3  = (const float*)d_in[10];
    const float* as3 = (const float*)d_in[11];
    const float* ad3 = (const float*)d_in[12];
    const float* b3  = (const float*)d_in[13];
    float* out = (float*)d_out;

    float *feat, *als, *ald, *alsP, *aldP;
    __nv_bfloat16* hbuf;
    int *off, *pos, *csrc;
    cudaGetSymbolAddress((void**)&feat, g_feat);
    cudaGetSymbolAddress((void**)&hbuf, g_hb);
    cudaGetSymbolAddress((void**)&als,  g_als);
    cudaGetSymbolAddress((void**)&ald,  g_ald);
    cudaGetSymbolAddress((void**)&alsP, g_alsP);
    cudaGetSymbolAddress((void**)&aldP, g_aldP);
    cudaGetSymbolAddress((void**)&off,  g_off);
    cudaGetSymbolAddress((void**)&pos,  g_pos);
    cudaGetSymbolAddress((void**)&csrc, g_csrc);

    static cudaStream_t s2 = 0;
    static cudaEvent_t evFork = 0, evJoin = 0;
    if (!s2) {
        cudaStreamCreate(&s2);
        cudaEventCreateWithFlags(&evFork, cudaEventDisableTiming);
        cudaEventCreateWithFlags(&evJoin, cudaEventDisableTiming);
    }

    // ---- fork: CSR build on s2, overlapped with layer-1 GEMM ----
    cudaEventRecord(evFork, 0);
    cudaStreamWaitEvent(s2, evFork, 0);
    zero_counts  <<<(NN + 255) / 256, 256, 0, s2>>>(pos);
    count_deg    <<<(ET + 255) / 256, 256, 0, s2>>>(ei, pos);
    scan_kernel  <<<1, 1024, 0, s2>>>(pos, off, pos);
    scatter_edges<<<(ET + 255) / 256, 256, 0, s2>>>(ei, pos, csrc);
    cudaEventRecord(evJoin, s2);

    dim3 gg(FDIM / 128, (NN + 63) / 64);

    // ---- layer 1 (H=4): GEMM(+attn) ; join CSR ; agg ----
    tf32gemm<<<gg, 256>>>(x, W1, hbuf, NN, 128, as1, ad1, als, ald, alsP, aldP, 4);
    cudaStreamWaitEvent(0, evJoin, 0);
    gat_agg<<<NN / 8, 256>>>(off, csrc, hbuf, als, ald, b1, feat, 4, 128, 1);

    // ---- layer 2 (H=4) ----
    tf32gemm<<<gg, 256>>>(feat, W2, hbuf, NN, 512, as2, ad2, als, ald, alsP, aldP, 4);
    gat_agg<<<NN / 8, 256>>>(off, csrc, hbuf, als, ald, b2, feat, 4, 128, 1);

    // ---- layer 3 (H=1): GEMM -> combine partials -> agg ----
    tf32gemm<<<gg, 256>>>(feat, W3, hbuf, NN, 512, as3, ad3, als, ald, alsP, aldP, 1);
    combine_attn<<<(NN + 255) / 256, 256>>>(alsP, aldP, als, ald);
    gat_agg<<<NN / 8, 256>>>(off, csrc, hbuf, als, ald, b3, out, 1, 512, 0);
}